// round 12
// baseline (speedup 1.0000x reference)
#include <cuda_runtime.h>

#define NQ 10
#define DEPTH 6
#define NF 1024
#define NC 10

typedef unsigned long long u64;

// ---------- f32x2 packed helpers ----------
__device__ __forceinline__ u64 pk(float x, float y) {
    u64 u; asm("mov.b64 %0,{%1,%2};" : "=l"(u) : "f"(x), "f"(y)); return u;
}
__device__ __forceinline__ u64 dup2(float x) { return pk(x, x); }
__device__ __forceinline__ void unpk(u64 u, float& x, float& y) {
    asm("mov.b64 {%0,%1},%2;" : "=f"(x), "=f"(y) : "l"(u));
}
__device__ __forceinline__ u64 fma2(u64 a, u64 b, u64 c) {
    u64 d; asm("fma.rn.f32x2 %0,%1,%2,%3;" : "=l"(d) : "l"(a), "l"(b), "l"(c)); return d;
}
__device__ __forceinline__ u64 mul2(u64 a, u64 b) {
    u64 d; asm("mul.rn.f32x2 %0,%1,%2;" : "=l"(d) : "l"(a), "l"(b)); return d;
}
__device__ __forceinline__ u64 add2(u64 a, u64 b) {
    u64 d; asm("add.rn.f32x2 %0,%1,%2;" : "=l"(d) : "l"(a), "l"(b)); return d;
}
__device__ __forceinline__ u64 sub2(u64 a, u64 b) {
    u64 d; asm("sub.rn.f32x2 %0,%1,%2;" : "=l"(d) : "l"(a), "l"(b)); return d;
}
__device__ __forceinline__ u64 neg2(u64 a) { return a ^ 0x8000000080000000ULL; }
__device__ __forceinline__ u64 rot32(u64 v) { return (v >> 32) | (v << 32); }

#define LOMASK 0x00000000FFFFFFFFULL
#define HIMASK 0xFFFFFFFF00000000ULL
#define FULLM 0xffffffffu

__device__ __forceinline__ float lsgn(int lane, int mask, float v) {
    return (__popc(lane & mask) & 1) ? -v : v;
}

// Amplitude index m (10 bits): bits0-4 = lane, bits5-8 = reg r (0..15), bit9 = u64 half.
// CNOT ring range R. Leading lane/lane run fused into one composed variable-source shuffle.
template <int R>
__device__ __forceinline__ void cnot_layer(u64 (&sr)[16], u64 (&si)[16], int lane) {
    constexpr int K = (R <= 4) ? (5 - R) : 0;
    if (K > 0) {
        int src = lane;
#pragma unroll
        for (int i = K - 1; i >= 0; i--) src ^= ((src >> i) & 1) << (i + R);
#pragma unroll
        for (int r = 0; r < 16; r++) {
            sr[r] = __shfl_sync(FULLM, sr[r], src);
            si[r] = __shfl_sync(FULLM, si[r], src);
        }
    }
#pragma unroll
    for (int i = K; i < NQ; i++) {
        const int c = i;
        const int t = (i + R) % NQ;
        if (c < 5 && t >= 5 && t < 9) {
            const int tb = 1 << (t - 5);
            bool ctrl = (lane >> c) & 1;
#pragma unroll
            for (int r0 = 0; r0 < 16; r0++)
                if (!(r0 & tb)) {
                    const int r1 = r0 | tb;
                    u64 t0 = sr[r0], t1 = si[r0];
                    sr[r0] = ctrl ? sr[r1] : sr[r0];
                    si[r0] = ctrl ? si[r1] : si[r0];
                    sr[r1] = ctrl ? t0 : sr[r1];
                    si[r1] = ctrl ? t1 : si[r1];
                }
        } else if (c < 5 && t == 9) {
            bool ctrl = (lane >> c) & 1;
#pragma unroll
            for (int r = 0; r < 16; r++) {
                u64 rr = rot32(sr[r]), ri = rot32(si[r]);
                sr[r] = ctrl ? rr : sr[r];
                si[r] = ctrl ? ri : si[r];
            }
        } else if (c >= 5 && c < 9 && t < 5) {
            const int cb = 1 << (c - 5);
#pragma unroll
            for (int r = 0; r < 16; r++)
                if (r & cb) {
                    sr[r] = __shfl_xor_sync(FULLM, sr[r], 1 << t);
                    si[r] = __shfl_xor_sync(FULLM, si[r], 1 << t);
                }
        } else if (c >= 5 && c < 9 && t >= 5 && t < 9) {
            const int cb = 1 << (c - 5), tb = 1 << (t - 5);
#pragma unroll
            for (int r0 = 0; r0 < 16; r0++)
                if ((r0 & cb) && !(r0 & tb)) {
                    const int r1 = r0 | tb;
                    u64 tmp = sr[r0]; sr[r0] = sr[r1]; sr[r1] = tmp;
                    tmp = si[r0]; si[r0] = si[r1]; si[r1] = tmp;
                }
        } else if (c >= 5 && c < 9 && t == 9) {
            const int cb = 1 << (c - 5);
#pragma unroll
            for (int r = 0; r < 16; r++)
                if (r & cb) {
                    sr[r] = rot32(sr[r]);
                    si[r] = rot32(si[r]);
                }
        } else if (c == 9 && t < 5) {
            // half ctrl / lane target: shuffle only the hi 32-bit words
#pragma unroll
            for (int r = 0; r < 16; r++) {
                unsigned hr_ = (unsigned)(sr[r] >> 32);
                unsigned hi_ = (unsigned)(si[r] >> 32);
                hr_ = __shfl_xor_sync(FULLM, hr_, 1 << t);
                hi_ = __shfl_xor_sync(FULLM, hi_, 1 << t);
                sr[r] = (sr[r] & LOMASK) | ((u64)hr_ << 32);
                si[r] = (si[r] & LOMASK) | ((u64)hi_ << 32);
            }
        } else {  // c == 9 && t in [5,9): swap hi halves between reg pairs
            const int tb = 1 << (t - 5);
#pragma unroll
            for (int r0 = 0; r0 < 16; r0++)
                if (!(r0 & tb)) {
                    const int r1 = r0 | tb;
                    u64 a = sr[r0], b = sr[r1];
                    sr[r0] = (a & LOMASK) | (b & HIMASK);
                    sr[r1] = (b & LOMASK) | (a & HIMASK);
                    a = si[r0]; b = si[r1];
                    si[r0] = (a & LOMASK) | (b & HIMASK);
                    si[r1] = (b & LOMASK) | (a & HIMASK);
                }
        }
    }
}

__global__ __launch_bounds__(128, 6) void fused_kernel(
    const float* __restrict__ x, const float* __restrict__ Wp,
    const float* __restrict__ w, const float* __restrict__ Wout,
    const float* __restrict__ bout, float* __restrict__ out, int B) {
    // SU(2) gate table: srot[g] = (alpha_r, alpha_i, beta_r, beta_i)
    __shared__ float4 srot[DEPTH * NQ];
    const int tid = threadIdx.x;
    if (tid < DEPTH * NQ) {
        float phi = w[tid * 3 + 0], theta = w[tid * 3 + 1], omega = w[tid * 3 + 2];
        float c, s;
        sincosf(0.5f * theta, &s, &c);
        float sp, cp, sm, cm;
        sincosf(-0.5f * (phi + omega), &sp, &cp);
        sincosf(-0.5f * (phi - omega), &sm, &cm);
        srot[tid] = make_float4(cp * c, sp * c, -cm * s, sm * s);
    }
    __syncthreads();

    const int warp = tid >> 5, lane = tid & 31;
    const int b = blockIdx.x * 4 + warp;
    if (b >= B) return;

    // ---- projection -> per-lane half-angle trig ----
    float myc = 0.f, mys = 0.f;
    {
        const float4* xv = (const float4*)(x + (size_t)b * NF);
        float acc[NQ];
#pragma unroll
        for (int q = 0; q < NQ; q++) acc[q] = 0.f;
#pragma unroll
        for (int it = 0; it < 8; it++) {
            float4 xx = xv[it * 32 + lane];
#pragma unroll
            for (int q = 0; q < NQ; q++) {
                float4 ww = __ldg(&((const float4*)(Wp + q * NF))[it * 32 + lane]);
                acc[q] += xx.x * ww.x + xx.y * ww.y + xx.z * ww.z + xx.w * ww.w;
            }
        }
#pragma unroll
        for (int off = 16; off > 0; off >>= 1)
#pragma unroll
            for (int q = 0; q < NQ; q++) acc[q] += __shfl_xor_sync(FULLM, acc[q], off);
        if (lane < NQ) {
            float v = acc[0];
#pragma unroll
            for (int q = 1; q < NQ; q++)
                if (lane == q) v = acc[q];
            float half = tanhf(v) * 0.78539816339744831f;
            sincosf(half, &mys, &myc);
        }
    }

    // ---- init: RY product state with layer-0 Rot folded in (array-free) ----
    float plr, pli;
    {
        plr = 1.f; pli = 0.f;
#pragma unroll
        for (int q = 0; q < 5; q++) {
            float cq = __shfl_sync(FULLM, myc, q);
            float sq = __shfl_sync(FULLM, mys, q);
            float4 G = srot[q];
            bool bq = (lane >> q) & 1;
            float wr = bq ? (-G.z * cq + G.x * sq) : (G.x * cq + G.z * sq);
            float wi = bq ? (G.w * cq - G.y * sq) : (G.y * cq + G.w * sq);
            float nr = plr * wr - pli * wi;
            float ni = plr * wi + pli * wr;
            plr = nr; pli = ni;
        }
    }
    u64 sr[16], si[16];
    {
        float ar2[4], ai2[4], br2[4], bi2[4];
        {
            float c5 = __shfl_sync(FULLM, myc, 5), s5 = __shfl_sync(FULLM, mys, 5);
            float c6 = __shfl_sync(FULLM, myc, 6), s6 = __shfl_sync(FULLM, mys, 6);
            float c7 = __shfl_sync(FULLM, myc, 7), s7 = __shfl_sync(FULLM, mys, 7);
            float c8 = __shfl_sync(FULLM, myc, 8), s8 = __shfl_sync(FULLM, mys, 8);
            float4 G5 = srot[5], G6 = srot[6], G7 = srot[7], G8 = srot[8];
            float v5r[2], v5i[2], v6r[2], v6i[2], v7r[2], v7i[2], v8r[2], v8i[2];
            v5r[0] = G5.x * c5 + G5.z * s5; v5i[0] = G5.y * c5 + G5.w * s5;
            v5r[1] = -G5.z * c5 + G5.x * s5; v5i[1] = G5.w * c5 - G5.y * s5;
            v6r[0] = G6.x * c6 + G6.z * s6; v6i[0] = G6.y * c6 + G6.w * s6;
            v6r[1] = -G6.z * c6 + G6.x * s6; v6i[1] = G6.w * c6 - G6.y * s6;
            v7r[0] = G7.x * c7 + G7.z * s7; v7i[0] = G7.y * c7 + G7.w * s7;
            v7r[1] = -G7.z * c7 + G7.x * s7; v7i[1] = G7.w * c7 - G7.y * s7;
            v8r[0] = G8.x * c8 + G8.z * s8; v8i[0] = G8.y * c8 + G8.w * s8;
            v8r[1] = -G8.z * c8 + G8.x * s8; v8i[1] = G8.w * c8 - G8.y * s8;
#pragma unroll
            for (int k = 0; k < 4; k++) {
                int b5 = k & 1, b6 = (k >> 1) & 1;
                ar2[k] = v5r[b5] * v6r[b6] - v5i[b5] * v6i[b6];
                ai2[k] = v5r[b5] * v6i[b6] + v5i[b5] * v6r[b6];
                br2[k] = v7r[b5] * v8r[b6] - v7i[b5] * v8i[b6];
                bi2[k] = v7r[b5] * v8i[b6] + v7i[b5] * v8r[b6];
            }
        }
        float c9 = __shfl_sync(FULLM, myc, 9), s9 = __shfl_sync(FULLM, mys, 9);
        float4 G9 = srot[9];
        u64 V9r = pk(G9.x * c9 + G9.z * s9, -G9.z * c9 + G9.x * s9);
        u64 V9i = pk(G9.y * c9 + G9.w * s9, G9.w * c9 - G9.y * s9);
#pragma unroll
        for (int r = 0; r < 16; r++) {
            float lr = ar2[r & 3], li = ai2[r & 3];
            float hr = br2[r >> 2], hi = bi2[r >> 2];
            float rpr = lr * hr - li * hi;
            float rpi = lr * hi + li * hr;
            float baser = plr * rpr - pli * rpi;
            float basei = plr * rpi + pli * rpr;
            u64 br_ = dup2(baser), bi_ = dup2(basei);
            sr[r] = sub2(mul2(br_, V9r), mul2(bi_, V9i));
            si[r] = fma2(br_, V9i, mul2(bi_, V9r));
        }
    }

    // ---- layer 0 entangler, then layers 1..5 (last ring folded into expvals) ----
    cnot_layer<1>(sr, si, lane);
#pragma unroll 1
    for (int l = 1; l < DEPTH; l++) {
#pragma unroll
        for (int q = 0; q < NQ; q++) {
            float4 G = srot[l * NQ + q];
            if (q >= 5 && q < 9) {
                // reg gate: 4 base constants; negations via sub2 (FMA pipe)
                u64 Ar = dup2(G.x), Ai = dup2(G.y), Br = dup2(G.z), Bi = dup2(G.w);
                const int jb = 1 << (q - 5);
#pragma unroll
                for (int r0 = 0; r0 < 16; r0++)
                    if (!(r0 & jb)) {
                        const int r1 = r0 | jb;
                        u64 a0r = sr[r0], a0i = si[r0];
                        u64 a1r = sr[r1], a1i = si[r1];
                        u64 s, p;
                        // n0r = (Ar a0r + Br a1r) - (Ai a0i + Bi a1i)
                        s = fma2(Br, a1r, mul2(Ar, a0r));
                        p = fma2(Bi, a1i, mul2(Ai, a0i));
                        sr[r0] = sub2(s, p);
                        // n0i = Ar a0i + Ai a0r + Br a1i + Bi a1r
                        s = fma2(Ai, a0r, mul2(Ar, a0i));
                        s = fma2(Br, a1i, s);
                        si[r0] = fma2(Bi, a1r, s);
                        // n1r = (Ar a1r + Ai a1i) - (Br a0r + Bi a0i)
                        s = fma2(Ai, a1i, mul2(Ar, a1r));
                        p = fma2(Bi, a0i, mul2(Br, a0r));
                        sr[r1] = sub2(s, p);
                        // n1i = (Ar a1i + Bi a0r) - (Ai a1r + Br a0i)
                        s = fma2(Bi, a0r, mul2(Ar, a1i));
                        p = fma2(Br, a0i, mul2(Ai, a1r));
                        si[r1] = sub2(s, p);
                    }
            } else if (q < 5) {
                bool hi = (lane >> q) & 1;
                float sai = hi ? -G.y : G.y;
                float sbr = hi ? -G.z : G.z;
                u64 Ar = dup2(G.x), Sai = dup2(sai), Sbr = dup2(sbr), Bi = dup2(G.w);
#pragma unroll
                for (int r = 0; r < 16; r++) {
                    u64 pr_ = __shfl_xor_sync(FULLM, sr[r], 1 << q);
                    u64 pi_ = __shfl_xor_sync(FULLM, si[r], 1 << q);
                    u64 mr = sr[r], mi = si[r];
                    u64 s, p;
                    // nr = (Ar mr + Sbr pr) - (Sai mi + Bi pi)
                    s = fma2(Sbr, pr_, mul2(Ar, mr));
                    p = fma2(Bi, pi_, mul2(Sai, mi));
                    sr[r] = sub2(s, p);
                    // ni = Ar mi + Sai mr + Sbr pi + Bi pr
                    s = fma2(Sai, mr, mul2(Ar, mi));
                    s = fma2(Sbr, pi_, s);
                    si[r] = fma2(Bi, pr_, s);
                }
            } else {  // q == 9: half-bit gate via rot32; packed (row0,row1) constants
                u64 K0r = dup2(G.x), K0i = pk(G.y, -G.y);
                u64 K1r = pk(G.z, -G.z), K1i = dup2(G.w);
#pragma unroll
                for (int r = 0; r < 16; r++) {
                    u64 mr = sr[r], mi = si[r];
                    u64 tr = rot32(mr), ti = rot32(mi);
                    u64 s, p;
                    // nr = (K0r mr + K1r tr) - (K0i mi + K1i ti)
                    s = fma2(K1r, tr, mul2(K0r, mr));
                    p = fma2(K1i, ti, mul2(K0i, mi));
                    sr[r] = sub2(s, p);
                    // ni = K0r mi + K0i mr + K1r ti + K1i tr
                    s = fma2(K0i, mr, mul2(K0r, mi));
                    s = fma2(K1r, ti, s);
                    si[r] = fma2(K1i, tr, s);
                }
            }
        }
        switch (l) {
            case 1: cnot_layer<2>(sr, si, lane); break;
            case 2: cnot_layer<3>(sr, si, lane); break;
            case 3: cnot_layer<4>(sr, si, lane); break;
            case 4: cnot_layer<5>(sr, si, lane); break;
            default: break;
        }
    }

    // ---- Z expvals with R=6 ring folded in as GF(2) parity masks ----
    u64 A0 = 0ULL, A1 = 0ULL, A2 = 0ULL, A4 = 0ULL, A8 = 0ULL;
#pragma unroll
    for (int r = 0; r < 16; r++) {
        u64 p = fma2(sr[r], sr[r], mul2(si[r], si[r]));
        u64 np = neg2(p);
        A0 = add2(A0, p);
        A1 = add2(A1, (r & 1) ? np : p);
        A2 = add2(A2, (r & 2) ? np : p);
        A4 = add2(A4, (r & 4) ? np : p);
        A8 = add2(A8, (r & 8) ? np : p);
    }
    u64 E[5];
    {
        float lo, hi;
        float e0, e1, e2, e3, e4, e5, e6, e7, e8, e9;
        unpk(A0, lo, hi);
        e0 = lsgn(lane, 0x11, lo + hi);
        e9 = lsgn(lane, 0x08, lo - hi);
        unpk(A1, lo, hi);
        e1 = lsgn(lane, 0x02, lo + hi);
        e5 = lsgn(lane, 0x08, lo - hi);
        unpk(A2, lo, hi);
        e2 = lsgn(lane, 0x05, lo + hi);
        e6 = lsgn(lane, 0x01, lo + hi);
        unpk(A4, lo, hi);
        e3 = lsgn(lane, 0x0A, lo + hi);
        e7 = lsgn(lane, 0x02, lo + hi);
        unpk(A8, lo, hi);
        e4 = lsgn(lane, 0x14, lo + hi);
        e8 = lsgn(lane, 0x04, lo + hi);
        E[0] = pk(e0, e1); E[1] = pk(e2, e3); E[2] = pk(e4, e5);
        E[3] = pk(e6, e7); E[4] = pk(e8, e9);
    }
#pragma unroll
    for (int off = 16; off > 0; off >>= 1)
#pragma unroll
        for (int k = 0; k < 5; k++)
            E[k] = add2(E[k], __shfl_xor_sync(FULLM, E[k], off));

    // ---- linear head ----
    if (lane < NC) {
        float e[NQ];
#pragma unroll
        for (int k = 0; k < 5; k++) unpk(E[k], e[2 * k], e[2 * k + 1]);
        float o = __ldg(&bout[lane]);
#pragma unroll
        for (int q = 0; q < NQ; q++) o += e[q] * __ldg(&Wout[lane * NQ + q]);
        out[(size_t)b * NC + lane] = o;
    }
}

extern "C" void kernel_launch(void* const* d_in, const int* in_sizes, int n_in,
                              void* d_out, int out_size) {
    const float* x = (const float*)d_in[0];
    const float* W_proj = (const float*)d_in[1];
    const float* weights = (const float*)d_in[2];
    const float* W_out = (const float*)d_in[3];
    const float* b_out = (const float*)d_in[4];
    float* out = (float*)d_out;

    int B = in_sizes[0] / NF;
    int nblk = (B + 3) / 4;

    fused_kernel<<<nblk, 128>>>(x, W_proj, weights, W_out, b_out, out, B);
}

// round 13
// speedup vs baseline: 1.1704x; 1.1704x over previous
#include <cuda_runtime.h>

#define NQ 10
#define DEPTH 6
#define NF 1024
#define NC 10

typedef unsigned long long u64;

// ---------- f32x2 packed helpers ----------
__device__ __forceinline__ u64 pk(float x, float y) {
    u64 u; asm("mov.b64 %0,{%1,%2};" : "=l"(u) : "f"(x), "f"(y)); return u;
}
__device__ __forceinline__ u64 dup2(float x) { return pk(x, x); }
__device__ __forceinline__ void unpk(u64 u, float& x, float& y) {
    asm("mov.b64 {%0,%1},%2;" : "=f"(x), "=f"(y) : "l"(u));
}
__device__ __forceinline__ u64 fma2(u64 a, u64 b, u64 c) {
    u64 d; asm("fma.rn.f32x2 %0,%1,%2,%3;" : "=l"(d) : "l"(a), "l"(b), "l"(c)); return d;
}
__device__ __forceinline__ u64 mul2(u64 a, u64 b) {
    u64 d; asm("mul.rn.f32x2 %0,%1,%2;" : "=l"(d) : "l"(a), "l"(b)); return d;
}
__device__ __forceinline__ u64 add2(u64 a, u64 b) {
    u64 d; asm("add.rn.f32x2 %0,%1,%2;" : "=l"(d) : "l"(a), "l"(b)); return d;
}
__device__ __forceinline__ u64 neg2(u64 a) { return a ^ 0x8000000080000000ULL; }
__device__ __forceinline__ u64 rot32(u64 v) { return (v >> 32) | (v << 32); }

#define LOMASK 0x00000000FFFFFFFFULL
#define HIMASK 0xFFFFFFFF00000000ULL
#define FULLM 0xffffffffu

__device__ __forceinline__ float lsgn(int lane, int mask, float v) {
    return (__popc(lane & mask) & 1) ? -v : v;
}

// lo-word lane mask for the fused trailing shuffle of ring R on reg r:
// XOR of (1<<(c+R-10)) over reg-bit controls c in [10-R, 8] whose bit is set in r.
template <int R>
__device__ __forceinline__ unsigned ring_mlo(int r) {
    unsigned m = 0;
#pragma unroll
    for (int c = 5; c <= 8; c++)
        if (c + R >= 10 && ((r >> (c - 5)) & 1)) m |= 1u << (c + R - 10);
    return m;
}

// Amplitude index m (10 bits): bits0-4 = lane, bits5-8 = reg r (0..15), bit9 = u64 half.
// CNOT ring range R (1..5):
//  - leading lane/lane gates (c=0..K-1, K=5-R): ONE composed variable-source shuffle
//  - lane-ctrl gates c=K..4 (reg/half targets): SEL swaps / conditional rot32
//  - reg-ctrl gates with t<=9: renames / subset rot32
//  - ALL remaining gates (reg/half ctrl -> lane target; c in [10-R,8] and c=9):
//    mutually commuting; fused into ONE per-reg two-mask word shuffle.
template <int R>
__device__ __forceinline__ void cnot_layer(u64 (&sr)[16], u64 (&si)[16], int lane) {
    constexpr int K = 5 - R;
    if (K > 0) {
        int src = lane;
#pragma unroll
        for (int i = K - 1; i >= 0; i--) src ^= ((src >> i) & 1) << (i + R);
#pragma unroll
        for (int r = 0; r < 16; r++) {
            sr[r] = __shfl_sync(FULLM, sr[r], src);
            si[r] = __shfl_sync(FULLM, si[r], src);
        }
    }
    // lane-ctrl gates c = K..4, t = c+R in [5,9]
#pragma unroll
    for (int c = K; c < 5; c++) {
        const int t = c + R;
        if (t < 9) {
            const int tb = 1 << (t - 5);
            bool ctrl = (lane >> c) & 1;
#pragma unroll
            for (int r0 = 0; r0 < 16; r0++)
                if (!(r0 & tb)) {
                    const int r1 = r0 | tb;
                    u64 t0 = sr[r0], t1 = si[r0];
                    sr[r0] = ctrl ? sr[r1] : sr[r0];
                    si[r0] = ctrl ? si[r1] : si[r0];
                    sr[r1] = ctrl ? t0 : sr[r1];
                    si[r1] = ctrl ? t1 : si[r1];
                }
        } else {  // t == 9: conditional half-swap
            bool ctrl = (lane >> c) & 1;
#pragma unroll
            for (int r = 0; r < 16; r++) {
                u64 rr = rot32(sr[r]), ri = rot32(si[r]);
                sr[r] = ctrl ? rr : sr[r];
                si[r] = ctrl ? ri : si[r];
            }
        }
    }
    // reg-ctrl gates with in-register targets: c = 5..min(8, 9-R)
#pragma unroll
    for (int c = 5; c <= 8; c++) {
        const int t = c + R;
        if (t <= 8) {
            // reg/reg rename
            const int cb = 1 << (c - 5), tb = 1 << (t - 5);
#pragma unroll
            for (int r0 = 0; r0 < 16; r0++)
                if ((r0 & cb) && !(r0 & tb)) {
                    const int r1 = r0 | tb;
                    u64 tmp = sr[r0]; sr[r0] = sr[r1]; sr[r1] = tmp;
                    tmp = si[r0]; si[r0] = si[r1]; si[r1] = tmp;
                }
        } else if (t == 9) {
            // reg-ctrl half-swap on subset
            const int cb = 1 << (c - 5);
#pragma unroll
            for (int r = 0; r < 16; r++)
                if (r & cb) {
                    sr[r] = rot32(sr[r]);
                    si[r] = rot32(si[r]);
                }
        }
        // t >= 10 handled by the fused shuffle below
    }
    // fused lane-target shuffle: c in [10-R, 8] (lo+hi words) and c=9 (hi word only)
#pragma unroll
    for (int r = 0; r < 16; r++) {
        const unsigned mlo = ring_mlo<R>(r);
        const unsigned mhi = mlo ^ (1u << (R - 1));  // always nonzero
        {
            unsigned lo = (unsigned)sr[r], hi = (unsigned)(sr[r] >> 32);
            if (mlo) lo = __shfl_xor_sync(FULLM, lo, mlo);
            hi = __shfl_xor_sync(FULLM, hi, mhi);
            sr[r] = (u64)lo | ((u64)hi << 32);
        }
        {
            unsigned lo = (unsigned)si[r], hi = (unsigned)(si[r] >> 32);
            if (mlo) lo = __shfl_xor_sync(FULLM, lo, mlo);
            hi = __shfl_xor_sync(FULLM, hi, mhi);
            si[r] = (u64)lo | ((u64)hi << 32);
        }
    }
}

__global__ __launch_bounds__(128, 5) void fused_kernel(
    const float* __restrict__ x, const float* __restrict__ Wp,
    const float* __restrict__ w, const float* __restrict__ Wout,
    const float* __restrict__ bout, float* __restrict__ out, int B) {
    // SU(2) gate table: srot[g] = (alpha_r, alpha_i, beta_r, beta_i)
    __shared__ float4 srot[DEPTH * NQ];
    const int tid = threadIdx.x;
    if (tid < DEPTH * NQ) {
        float phi = w[tid * 3 + 0], theta = w[tid * 3 + 1], omega = w[tid * 3 + 2];
        float c, s;
        sincosf(0.5f * theta, &s, &c);
        float sp, cp, sm, cm;
        sincosf(-0.5f * (phi + omega), &sp, &cp);
        sincosf(-0.5f * (phi - omega), &sm, &cm);
        srot[tid] = make_float4(cp * c, sp * c, -cm * s, sm * s);
    }
    __syncthreads();

    const int warp = tid >> 5, lane = tid & 31;
    const int b = blockIdx.x * 4 + warp;
    if (b >= B) return;

    // ---- projection -> per-lane half-angle trig ----
    float myc = 0.f, mys = 0.f;
    {
        const float4* xv = (const float4*)(x + (size_t)b * NF);
        float acc[NQ];
#pragma unroll
        for (int q = 0; q < NQ; q++) acc[q] = 0.f;
#pragma unroll
        for (int it = 0; it < 8; it++) {
            float4 xx = xv[it * 32 + lane];
#pragma unroll
            for (int q = 0; q < NQ; q++) {
                float4 ww = __ldg(&((const float4*)(Wp + q * NF))[it * 32 + lane]);
                acc[q] += xx.x * ww.x + xx.y * ww.y + xx.z * ww.z + xx.w * ww.w;
            }
        }
#pragma unroll
        for (int off = 16; off > 0; off >>= 1)
#pragma unroll
            for (int q = 0; q < NQ; q++) acc[q] += __shfl_xor_sync(FULLM, acc[q], off);
        if (lane < NQ) {
            float v = acc[0];
#pragma unroll
            for (int q = 1; q < NQ; q++)
                if (lane == q) v = acc[q];
            float half = tanhf(v) * 0.78539816339744831f;
            sincosf(half, &mys, &myc);
        }
    }

    // ---- init: RY product state with layer-0 Rot folded in (array-free) ----
    float plr, pli;
    {
        plr = 1.f; pli = 0.f;
#pragma unroll
        for (int q = 0; q < 5; q++) {
            float cq = __shfl_sync(FULLM, myc, q);
            float sq = __shfl_sync(FULLM, mys, q);
            float4 G = srot[q];
            bool bq = (lane >> q) & 1;
            float wr = bq ? (-G.z * cq + G.x * sq) : (G.x * cq + G.z * sq);
            float wi = bq ? (G.w * cq - G.y * sq) : (G.y * cq + G.w * sq);
            float nr = plr * wr - pli * wi;
            float ni = plr * wi + pli * wr;
            plr = nr; pli = ni;
        }
    }
    u64 sr[16], si[16];
    {
        float ar2[4], ai2[4], br2[4], bi2[4];
        {
            float c5 = __shfl_sync(FULLM, myc, 5), s5 = __shfl_sync(FULLM, mys, 5);
            float c6 = __shfl_sync(FULLM, myc, 6), s6 = __shfl_sync(FULLM, mys, 6);
            float c7 = __shfl_sync(FULLM, myc, 7), s7 = __shfl_sync(FULLM, mys, 7);
            float c8 = __shfl_sync(FULLM, myc, 8), s8 = __shfl_sync(FULLM, mys, 8);
            float4 G5 = srot[5], G6 = srot[6], G7 = srot[7], G8 = srot[8];
            float v5r[2], v5i[2], v6r[2], v6i[2], v7r[2], v7i[2], v8r[2], v8i[2];
            v5r[0] = G5.x * c5 + G5.z * s5; v5i[0] = G5.y * c5 + G5.w * s5;
            v5r[1] = -G5.z * c5 + G5.x * s5; v5i[1] = G5.w * c5 - G5.y * s5;
            v6r[0] = G6.x * c6 + G6.z * s6; v6i[0] = G6.y * c6 + G6.w * s6;
            v6r[1] = -G6.z * c6 + G6.x * s6; v6i[1] = G6.w * c6 - G6.y * s6;
            v7r[0] = G7.x * c7 + G7.z * s7; v7i[0] = G7.y * c7 + G7.w * s7;
            v7r[1] = -G7.z * c7 + G7.x * s7; v7i[1] = G7.w * c7 - G7.y * s7;
            v8r[0] = G8.x * c8 + G8.z * s8; v8i[0] = G8.y * c8 + G8.w * s8;
            v8r[1] = -G8.z * c8 + G8.x * s8; v8i[1] = G8.w * c8 - G8.y * s8;
#pragma unroll
            for (int k = 0; k < 4; k++) {
                int b5 = k & 1, b6 = (k >> 1) & 1;
                ar2[k] = v5r[b5] * v6r[b6] - v5i[b5] * v6i[b6];
                ai2[k] = v5r[b5] * v6i[b6] + v5i[b5] * v6r[b6];
                br2[k] = v7r[b5] * v8r[b6] - v7i[b5] * v8i[b6];
                bi2[k] = v7r[b5] * v8i[b6] + v7i[b5] * v8r[b6];
            }
        }
        float c9 = __shfl_sync(FULLM, myc, 9), s9 = __shfl_sync(FULLM, mys, 9);
        float4 G9 = srot[9];
        u64 V9r = pk(G9.x * c9 + G9.z * s9, -G9.z * c9 + G9.x * s9);
        u64 V9i = pk(G9.y * c9 + G9.w * s9, G9.w * c9 - G9.y * s9);
#pragma unroll
        for (int r = 0; r < 16; r++) {
            float lr = ar2[r & 3], li = ai2[r & 3];
            float hr = br2[r >> 2], hi = bi2[r >> 2];
            float rpr = lr * hr - li * hi;
            float rpi = lr * hi + li * hr;
            float baser = plr * rpr - pli * rpi;
            float basei = plr * rpi + pli * rpr;
            u64 br_ = dup2(baser), bi_ = dup2(basei);
            sr[r] = fma2(br_, V9r, mul2(neg2(bi_), V9i));
            si[r] = fma2(br_, V9i, mul2(bi_, V9r));
        }
    }

    // ---- layer 0 entangler, then layers 1..5 (last ring folded into expvals) ----
    cnot_layer<1>(sr, si, lane);
#pragma unroll 1
    for (int l = 1; l < DEPTH; l++) {
#pragma unroll
        for (int q = 0; q < NQ; q++) {
            float4 G = srot[l * NQ + q];
            if (q >= 5 && q < 9) {
                // reg gate: pure-FMA body, negated constants precomputed
                u64 Ar = dup2(G.x), Ai = dup2(G.y), Ain = dup2(-G.y);
                u64 Br = dup2(G.z), Brn = dup2(-G.z);
                u64 Bi = dup2(G.w), Bin = dup2(-G.w);
                const int jb = 1 << (q - 5);
#pragma unroll
                for (int r0 = 0; r0 < 16; r0++)
                    if (!(r0 & jb)) {
                        const int r1 = r0 | jb;
                        u64 a0r = sr[r0], a0i = si[r0];
                        u64 a1r = sr[r1], a1i = si[r1];
                        u64 t;
                        t = mul2(Bin, a1i); t = fma2(Br, a1r, t); t = fma2(Ain, a0i, t);
                        sr[r0] = fma2(Ar, a0r, t);
                        t = mul2(Bi, a1r); t = fma2(Br, a1i, t); t = fma2(Ai, a0r, t);
                        si[r0] = fma2(Ar, a0i, t);
                        t = mul2(Bin, a0i); t = fma2(Brn, a0r, t); t = fma2(Ai, a1i, t);
                        sr[r1] = fma2(Ar, a1r, t);
                        t = mul2(Bi, a0r); t = fma2(Brn, a0i, t); t = fma2(Ain, a1r, t);
                        si[r1] = fma2(Ar, a1i, t);
                    }
            } else if (q < 5) {
                bool hi = (lane >> q) & 1;
                float sai = hi ? -G.y : G.y;
                float sbr = hi ? -G.z : G.z;
                u64 Ar = dup2(G.x), Sai = dup2(sai), Sain = dup2(-sai);
                u64 Sbr = dup2(sbr), Bi = dup2(G.w), Bin = dup2(-G.w);
#pragma unroll
                for (int r = 0; r < 16; r++) {
                    u64 pr_ = __shfl_xor_sync(FULLM, sr[r], 1 << q);
                    u64 pi_ = __shfl_xor_sync(FULLM, si[r], 1 << q);
                    u64 mr = sr[r], mi = si[r];
                    u64 t;
                    t = mul2(Bin, pi_); t = fma2(Sbr, pr_, t); t = fma2(Sain, mi, t);
                    sr[r] = fma2(Ar, mr, t);
                    t = mul2(Bi, pr_); t = fma2(Sbr, pi_, t); t = fma2(Sai, mr, t);
                    si[r] = fma2(Ar, mi, t);
                }
            } else {  // q == 9: half-bit gate via rot32; packed (row0,row1) constants
                u64 K0r = dup2(G.x), K0i = pk(G.y, -G.y), K0in = pk(-G.y, G.y);
                u64 K1r = pk(G.z, -G.z), K1i = dup2(G.w), K1in = dup2(-G.w);
#pragma unroll
                for (int r = 0; r < 16; r++) {
                    u64 mr = sr[r], mi = si[r];
                    u64 tr = rot32(mr), ti = rot32(mi);
                    u64 t;
                    t = mul2(K1in, ti); t = fma2(K1r, tr, t); t = fma2(K0in, mi, t);
                    sr[r] = fma2(K0r, mr, t);
                    t = mul2(K1i, tr); t = fma2(K1r, ti, t); t = fma2(K0i, mr, t);
                    si[r] = fma2(K0r, mi, t);
                }
            }
        }
        switch (l) {
            case 1: cnot_layer<2>(sr, si, lane); break;
            case 2: cnot_layer<3>(sr, si, lane); break;
            case 3: cnot_layer<4>(sr, si, lane); break;
            case 4: cnot_layer<5>(sr, si, lane); break;
            default: break;
        }
    }

    // ---- Z expvals with R=6 ring folded in as GF(2) parity masks ----
    u64 A0 = 0ULL, A1 = 0ULL, A2 = 0ULL, A4 = 0ULL, A8 = 0ULL;
#pragma unroll
    for (int r = 0; r < 16; r++) {
        u64 p = fma2(sr[r], sr[r], mul2(si[r], si[r]));
        u64 np = neg2(p);
        A0 = add2(A0, p);
        A1 = add2(A1, (r & 1) ? np : p);
        A2 = add2(A2, (r & 2) ? np : p);
        A4 = add2(A4, (r & 4) ? np : p);
        A8 = add2(A8, (r & 8) ? np : p);
    }
    u64 E[5];
    {
        float lo, hi;
        float e0, e1, e2, e3, e4, e5, e6, e7, e8, e9;
        unpk(A0, lo, hi);
        e0 = lsgn(lane, 0x11, lo + hi);
        e9 = lsgn(lane, 0x08, lo - hi);
        unpk(A1, lo, hi);
        e1 = lsgn(lane, 0x02, lo + hi);
        e5 = lsgn(lane, 0x08, lo - hi);
        unpk(A2, lo, hi);
        e2 = lsgn(lane, 0x05, lo + hi);
        e6 = lsgn(lane, 0x01, lo + hi);
        unpk(A4, lo, hi);
        e3 = lsgn(lane, 0x0A, lo + hi);
        e7 = lsgn(lane, 0x02, lo + hi);
        unpk(A8, lo, hi);
        e4 = lsgn(lane, 0x14, lo + hi);
        e8 = lsgn(lane, 0x04, lo + hi);
        E[0] = pk(e0, e1); E[1] = pk(e2, e3); E[2] = pk(e4, e5);
        E[3] = pk(e6, e7); E[4] = pk(e8, e9);
    }
#pragma unroll
    for (int off = 16; off > 0; off >>= 1)
#pragma unroll
        for (int k = 0; k < 5; k++)
            E[k] = add2(E[k], __shfl_xor_sync(FULLM, E[k], off));

    // ---- linear head ----
    if (lane < NC) {
        float e[NQ];
#pragma unroll
        for (int k = 0; k < 5; k++) unpk(E[k], e[2 * k], e[2 * k + 1]);
        float o = __ldg(&bout[lane]);
#pragma unroll
        for (int q = 0; q < NQ; q++) o += e[q] * __ldg(&Wout[lane * NQ + q]);
        out[(size_t)b * NC + lane] = o;
    }
}

extern "C" void kernel_launch(void* const* d_in, const int* in_sizes, int n_in,
                              void* d_out, int out_size) {
    const float* x = (const float*)d_in[0];
    const float* W_proj = (const float*)d_in[1];
    const float* weights = (const float*)d_in[2];
    const float* W_out = (const float*)d_in[3];
    const float* b_out = (const float*)d_in[4];
    float* out = (float*)d_out;

    int B = in_sizes[0] / NF;
    int nblk = (B + 3) / 4;

    fused_kernel<<<nblk, 128>>>(x, W_proj, weights, W_out, b_out, out, B);
}

// round 14
// speedup vs baseline: 1.4941x; 1.2766x over previous
#include <cuda_runtime.h>

#define NQ 10
#define DEPTH 6
#define NF 1024
#define NC 10

typedef unsigned long long u64;

// Transition diagonals: T_l (l=1..5), 512 float4 each:
// entry [(l-1)*512 + r*32 + lane] = (re_lo, re_hi, im_lo, im_hi) for m = lane|(r<<5), halves = q9
__device__ float4 g_diag[5 * 512];

// ---------- f32x2 packed helpers ----------
__device__ __forceinline__ u64 pk(float x, float y) {
    u64 u; asm("mov.b64 %0,{%1,%2};" : "=l"(u) : "f"(x), "f"(y)); return u;
}
__device__ __forceinline__ u64 dup2(float x) { return pk(x, x); }
__device__ __forceinline__ void unpk(u64 u, float& x, float& y) {
    asm("mov.b64 {%0,%1},%2;" : "=f"(x), "=f"(y) : "l"(u));
}
__device__ __forceinline__ u64 fma2(u64 a, u64 b, u64 c) {
    u64 d; asm("fma.rn.f32x2 %0,%1,%2,%3;" : "=l"(d) : "l"(a), "l"(b), "l"(c)); return d;
}
__device__ __forceinline__ u64 mul2(u64 a, u64 b) {
    u64 d; asm("mul.rn.f32x2 %0,%1,%2;" : "=l"(d) : "l"(a), "l"(b)); return d;
}
__device__ __forceinline__ u64 add2(u64 a, u64 b) {
    u64 d; asm("add.rn.f32x2 %0,%1,%2;" : "=l"(d) : "l"(a), "l"(b)); return d;
}
__device__ __forceinline__ u64 sub2(u64 a, u64 b) {
    u64 d; asm("sub.rn.f32x2 %0,%1,%2;" : "=l"(d) : "l"(a), "l"(b)); return d;
}
__device__ __forceinline__ u64 neg2(u64 a) { return a ^ 0x8000000080000000ULL; }
__device__ __forceinline__ u64 rot32(u64 v) { return (v >> 32) | (v << 32); }

#define LOMASK 0x00000000FFFFFFFFULL
#define HIMASK 0xFFFFFFFF00000000ULL
#define FULLM 0xffffffffu

__device__ __forceinline__ float lsgn(int lane, int mask, float v) {
    return (__popc(lane & mask) & 1) ? -v : v;
}

// ring source map sigma for ring range R: s ^= bit_i(s) << ((i+R)%10), i = 9..0
__device__ __forceinline__ int ring_sigma(int m, int R) {
    int s = m;
    for (int i = 9; i >= 0; i--) {
        int tt = i + R;
        if (tt >= 10) tt -= 10;
        s ^= ((s >> i) & 1) << tt;
    }
    return s;
}

// Prep kernel: build the 5 transition diagonals.
// T_1(m) = prod_q phiphase_{1,q}(bit_q(m))
// T_l(m) = prod_q phiphase_{l,q}(bit_q(m)) * prod_q omegaphase_{l-1,q}(bit_q(sigma_l(m))), l>=2
// phase(b) = exp(i * ang/2 * (2b-1))
__global__ void build_diag(const float* __restrict__ w) {
    int l = blockIdx.x + 1;   // 1..5
    int m = threadIdx.x;      // 0..511 (half = 0)
    float res[2], ims[2];
#pragma unroll
    for (int half = 0; half < 2; half++) {
        int mm = m | (half << 9);
        float dr = 1.f, di = 0.f;
        // phi of layer l at bits of mm
        for (int q = 0; q < NQ; q++) {
            float a = 0.5f * w[(l * NQ + q) * 3 + 0];
            int b = (mm >> q) & 1;
            float cc, ss;
            sincosf(b ? a : -a, &ss, &cc);
            float nr = dr * cc - di * ss;
            float ni = dr * ss + di * cc;
            dr = nr; di = ni;
        }
        if (l >= 2) {
            int s = ring_sigma(mm, l);
            for (int q = 0; q < NQ; q++) {
                float a = 0.5f * w[((l - 1) * NQ + q) * 3 + 2];
                int b = (s >> q) & 1;
                float cc, ss;
                sincosf(b ? a : -a, &ss, &cc);
                float nr = dr * cc - di * ss;
                float ni = dr * ss + di * cc;
                dr = nr; di = ni;
            }
        }
        res[half] = dr; ims[half] = di;
    }
    g_diag[(l - 1) * 512 + m] = make_float4(res[0], res[1], ims[0], ims[1]);
}

// Amplitude index m: bits0-4 = lane, bits5-8 = reg r (0..15), bit9 = u64 half.
// CNOT ring range R (1..5) with fused leading + trailing shuffles (round-13 winner).
template <int R>
__device__ __forceinline__ unsigned ring_mlo(int r) {
    unsigned m = 0;
#pragma unroll
    for (int c = 5; c <= 8; c++)
        if (c + R >= 10 && ((r >> (c - 5)) & 1)) m |= 1u << (c + R - 10);
    return m;
}

template <int R>
__device__ __forceinline__ void cnot_layer(u64 (&sr)[16], u64 (&si)[16], int lane) {
    constexpr int K = 5 - R;
    if (K > 0) {
        int src = lane;
#pragma unroll
        for (int i = K - 1; i >= 0; i--) src ^= ((src >> i) & 1) << (i + R);
#pragma unroll
        for (int r = 0; r < 16; r++) {
            sr[r] = __shfl_sync(FULLM, sr[r], src);
            si[r] = __shfl_sync(FULLM, si[r], src);
        }
    }
#pragma unroll
    for (int c = K; c < 5; c++) {
        const int t = c + R;
        if (t < 9) {
            const int tb = 1 << (t - 5);
            bool ctrl = (lane >> c) & 1;
#pragma unroll
            for (int r0 = 0; r0 < 16; r0++)
                if (!(r0 & tb)) {
                    const int r1 = r0 | tb;
                    u64 t0 = sr[r0], t1 = si[r0];
                    sr[r0] = ctrl ? sr[r1] : sr[r0];
                    si[r0] = ctrl ? si[r1] : si[r0];
                    sr[r1] = ctrl ? t0 : sr[r1];
                    si[r1] = ctrl ? t1 : si[r1];
                }
        } else {  // t == 9
            bool ctrl = (lane >> c) & 1;
#pragma unroll
            for (int r = 0; r < 16; r++) {
                u64 rr = rot32(sr[r]), ri = rot32(si[r]);
                sr[r] = ctrl ? rr : sr[r];
                si[r] = ctrl ? ri : si[r];
            }
        }
    }
#pragma unroll
    for (int c = 5; c <= 8; c++) {
        const int t = c + R;
        if (t <= 8) {
            const int cb = 1 << (c - 5), tb = 1 << (t - 5);
#pragma unroll
            for (int r0 = 0; r0 < 16; r0++)
                if ((r0 & cb) && !(r0 & tb)) {
                    const int r1 = r0 | tb;
                    u64 tmp = sr[r0]; sr[r0] = sr[r1]; sr[r1] = tmp;
                    tmp = si[r0]; si[r0] = si[r1]; si[r1] = tmp;
                }
        } else if (t == 9) {
            const int cb = 1 << (c - 5);
#pragma unroll
            for (int r = 0; r < 16; r++)
                if (r & cb) {
                    sr[r] = rot32(sr[r]);
                    si[r] = rot32(si[r]);
                }
        }
    }
#pragma unroll
    for (int r = 0; r < 16; r++) {
        const unsigned mlo = ring_mlo<R>(r);
        const unsigned mhi = mlo ^ (1u << (R - 1));
        {
            unsigned lo = (unsigned)sr[r], hi = (unsigned)(sr[r] >> 32);
            if (mlo) lo = __shfl_xor_sync(FULLM, lo, mlo);
            hi = __shfl_xor_sync(FULLM, hi, mhi);
            sr[r] = (u64)lo | ((u64)hi << 32);
        }
        {
            unsigned lo = (unsigned)si[r], hi = (unsigned)(si[r] >> 32);
            if (mlo) lo = __shfl_xor_sync(FULLM, lo, mlo);
            hi = __shfl_xor_sync(FULLM, hi, mhi);
            si[r] = (u64)lo | ((u64)hi << 32);
        }
    }
}

__global__ __launch_bounds__(128, 5) void fused_kernel(
    const float* __restrict__ x, const float* __restrict__ Wp,
    const float* __restrict__ w, const float* __restrict__ Wout,
    const float* __restrict__ bout, float* __restrict__ out, int B) {
    // layer-0 full SU(2) gates + RY(theta) coefficients for layers 1..5
    __shared__ float4 rot0[NQ];
    __shared__ float2 sry[5 * NQ];
    const int tid = threadIdx.x;
    if (tid < DEPTH * NQ) {
        float theta = w[tid * 3 + 1];
        float c, s;
        sincosf(0.5f * theta, &s, &c);
        if (tid < NQ) {
            float phi = w[tid * 3 + 0], omega = w[tid * 3 + 2];
            float sp, cp, sm, cm;
            sincosf(-0.5f * (phi + omega), &sp, &cp);
            sincosf(-0.5f * (phi - omega), &sm, &cm);
            rot0[tid] = make_float4(cp * c, sp * c, -cm * s, sm * s);
        } else {
            sry[tid - NQ] = make_float2(c, s);
        }
    }
    __syncthreads();

    const int warp = tid >> 5, lane = tid & 31;
    const int b = blockIdx.x * 4 + warp;
    if (b >= B) return;

    // ---- projection -> per-lane half-angle trig ----
    float myc = 0.f, mys = 0.f;
    {
        const float4* xv = (const float4*)(x + (size_t)b * NF);
        float acc[NQ];
#pragma unroll
        for (int q = 0; q < NQ; q++) acc[q] = 0.f;
#pragma unroll
        for (int it = 0; it < 8; it++) {
            float4 xx = xv[it * 32 + lane];
#pragma unroll
            for (int q = 0; q < NQ; q++) {
                float4 ww = __ldg(&((const float4*)(Wp + q * NF))[it * 32 + lane]);
                acc[q] += xx.x * ww.x + xx.y * ww.y + xx.z * ww.z + xx.w * ww.w;
            }
        }
#pragma unroll
        for (int off = 16; off > 0; off >>= 1)
#pragma unroll
            for (int q = 0; q < NQ; q++) acc[q] += __shfl_xor_sync(FULLM, acc[q], off);
        if (lane < NQ) {
            float v = acc[0];
#pragma unroll
            for (int q = 1; q < NQ; q++)
                if (lane == q) v = acc[q];
            float half = tanhf(v) * 0.78539816339744831f;
            sincosf(half, &mys, &myc);
        }
    }

    // ---- init: RY product state with FULL layer-0 Rot folded in ----
    float plr, pli;
    {
        plr = 1.f; pli = 0.f;
#pragma unroll
        for (int q = 0; q < 5; q++) {
            float cq = __shfl_sync(FULLM, myc, q);
            float sq = __shfl_sync(FULLM, mys, q);
            float4 G = rot0[q];
            bool bq = (lane >> q) & 1;
            float wr = bq ? (-G.z * cq + G.x * sq) : (G.x * cq + G.z * sq);
            float wi = bq ? (G.w * cq - G.y * sq) : (G.y * cq + G.w * sq);
            float nr = plr * wr - pli * wi;
            float ni = plr * wi + pli * wr;
            plr = nr; pli = ni;
        }
    }
    u64 sr[16], si[16];
    {
        float ar2[4], ai2[4], br2[4], bi2[4];
        {
            float c5 = __shfl_sync(FULLM, myc, 5), s5 = __shfl_sync(FULLM, mys, 5);
            float c6 = __shfl_sync(FULLM, myc, 6), s6 = __shfl_sync(FULLM, mys, 6);
            float c7 = __shfl_sync(FULLM, myc, 7), s7 = __shfl_sync(FULLM, mys, 7);
            float c8 = __shfl_sync(FULLM, myc, 8), s8 = __shfl_sync(FULLM, mys, 8);
            float4 G5 = rot0[5], G6 = rot0[6], G7 = rot0[7], G8 = rot0[8];
            float v5r[2], v5i[2], v6r[2], v6i[2], v7r[2], v7i[2], v8r[2], v8i[2];
            v5r[0] = G5.x * c5 + G5.z * s5; v5i[0] = G5.y * c5 + G5.w * s5;
            v5r[1] = -G5.z * c5 + G5.x * s5; v5i[1] = G5.w * c5 - G5.y * s5;
            v6r[0] = G6.x * c6 + G6.z * s6; v6i[0] = G6.y * c6 + G6.w * s6;
            v6r[1] = -G6.z * c6 + G6.x * s6; v6i[1] = G6.w * c6 - G6.y * s6;
            v7r[0] = G7.x * c7 + G7.z * s7; v7i[0] = G7.y * c7 + G7.w * s7;
            v7r[1] = -G7.z * c7 + G7.x * s7; v7i[1] = G7.w * c7 - G7.y * s7;
            v8r[0] = G8.x * c8 + G8.z * s8; v8i[0] = G8.y * c8 + G8.w * s8;
            v8r[1] = -G8.z * c8 + G8.x * s8; v8i[1] = G8.w * c8 - G8.y * s8;
#pragma unroll
            for (int k = 0; k < 4; k++) {
                int b5 = k & 1, b6 = (k >> 1) & 1;
                ar2[k] = v5r[b5] * v6r[b6] - v5i[b5] * v6i[b6];
                ai2[k] = v5r[b5] * v6i[b6] + v5i[b5] * v6r[b6];
                br2[k] = v7r[b5] * v8r[b6] - v7i[b5] * v8i[b6];
                bi2[k] = v7r[b5] * v8i[b6] + v7i[b5] * v8r[b6];
            }
        }
        float c9 = __shfl_sync(FULLM, myc, 9), s9 = __shfl_sync(FULLM, mys, 9);
        float4 G9 = rot0[9];
        u64 V9r = pk(G9.x * c9 + G9.z * s9, -G9.z * c9 + G9.x * s9);
        u64 V9i = pk(G9.y * c9 + G9.w * s9, G9.w * c9 - G9.y * s9);
#pragma unroll
        for (int r = 0; r < 16; r++) {
            float lr = ar2[r & 3], li = ai2[r & 3];
            float hr = br2[r >> 2], hi = bi2[r >> 2];
            float rpr = lr * hr - li * hi;
            float rpi = lr * hi + li * hr;
            float baser = plr * rpr - pli * rpi;
            float basei = plr * rpi + pli * rpr;
            u64 br_ = dup2(baser), bi_ = dup2(basei);
            sr[r] = fma2(br_, V9r, mul2(neg2(bi_), V9i));
            si[r] = fma2(br_, V9i, mul2(bi_, V9r));
        }
    }

    // ---- ring 1, then layers 1..5: [diag T_l] [RY gates]; rings 2..5 between ----
    cnot_layer<1>(sr, si, lane);
#pragma unroll 1
    for (int l = 1; l < DEPTH; l++) {
        // transition diagonal T_l (phi_l merged with pushed omega_{l-1})
        {
            const float4* dtab = &g_diag[(l - 1) * 512];
#pragma unroll
            for (int r = 0; r < 16; r++) {
                float4 d = __ldg(&dtab[r * 32 + lane]);
                u64 drk = pk(d.x, d.y), dik = pk(d.z, d.w);
                u64 mr = sr[r], mi = si[r];
                sr[r] = sub2(mul2(drk, mr), mul2(dik, mi));
                si[r] = fma2(drk, mi, mul2(dik, mr));
            }
        }
        // RY lane gates q0..q4 (real coefficients)
#pragma unroll
        for (int q = 0; q < 5; q++) {
            float2 cs = sry[(l - 1) * NQ + q];
            bool hb = (lane >> q) & 1;
            u64 C = dup2(cs.x), S = dup2(hb ? cs.y : -cs.y);
#pragma unroll
            for (int r = 0; r < 16; r++) {
                u64 pr_ = __shfl_xor_sync(FULLM, sr[r], 1 << q);
                u64 pi_ = __shfl_xor_sync(FULLM, si[r], 1 << q);
                sr[r] = fma2(C, sr[r], mul2(S, pr_));
                si[r] = fma2(C, si[r], mul2(S, pi_));
            }
        }
        // RY reg gates q5..q8
#pragma unroll
        for (int q = 5; q < 9; q++) {
            float2 cs = sry[(l - 1) * NQ + q];
            u64 C = dup2(cs.x), S = dup2(cs.y), Sn = dup2(-cs.y);
            const int jb = 1 << (q - 5);
#pragma unroll
            for (int r0 = 0; r0 < 16; r0++)
                if (!(r0 & jb)) {
                    const int r1 = r0 | jb;
                    u64 a0r = sr[r0], a0i = si[r0];
                    u64 a1r = sr[r1], a1i = si[r1];
                    sr[r0] = fma2(C, a0r, mul2(Sn, a1r));
                    si[r0] = fma2(C, a0i, mul2(Sn, a1i));
                    sr[r1] = fma2(C, a1r, mul2(S, a0r));
                    si[r1] = fma2(C, a1i, mul2(S, a0i));
                }
        }
        // RY half gate q9: lo' = c*lo - s*hi ; hi' = c*hi + s*lo
        {
            float2 cs = sry[(l - 1) * NQ + 9];
            u64 C = dup2(cs.x), Spk = pk(-cs.y, cs.y);
#pragma unroll
            for (int r = 0; r < 16; r++) {
                u64 tr = rot32(sr[r]), ti = rot32(si[r]);
                sr[r] = fma2(C, sr[r], mul2(Spk, tr));
                si[r] = fma2(C, si[r], mul2(Spk, ti));
            }
        }
        switch (l) {
            case 1: cnot_layer<2>(sr, si, lane); break;
            case 2: cnot_layer<3>(sr, si, lane); break;
            case 3: cnot_layer<4>(sr, si, lane); break;
            case 4: cnot_layer<5>(sr, si, lane); break;
            default: break;  // layer 5: omega_5 diag dropped (phase-invariant), ring 6 folded below
        }
    }

    // ---- Z expvals with R=6 ring folded in as GF(2) parity masks ----
    u64 A0 = 0ULL, A1 = 0ULL, A2 = 0ULL, A4 = 0ULL, A8 = 0ULL;
#pragma unroll
    for (int r = 0; r < 16; r++) {
        u64 p = fma2(sr[r], sr[r], mul2(si[r], si[r]));
        u64 np = neg2(p);
        A0 = add2(A0, p);
        A1 = add2(A1, (r & 1) ? np : p);
        A2 = add2(A2, (r & 2) ? np : p);
        A4 = add2(A4, (r & 4) ? np : p);
        A8 = add2(A8, (r & 8) ? np : p);
    }
    u64 E[5];
    {
        float lo, hi;
        float e0, e1, e2, e3, e4, e5, e6, e7, e8, e9;
        unpk(A0, lo, hi);
        e0 = lsgn(lane, 0x11, lo + hi);
        e9 = lsgn(lane, 0x08, lo - hi);
        unpk(A1, lo, hi);
        e1 = lsgn(lane, 0x02, lo + hi);
        e5 = lsgn(lane, 0x08, lo - hi);
        unpk(A2, lo, hi);
        e2 = lsgn(lane, 0x05, lo + hi);
        e6 = lsgn(lane, 0x01, lo + hi);
        unpk(A4, lo, hi);
        e3 = lsgn(lane, 0x0A, lo + hi);
        e7 = lsgn(lane, 0x02, lo + hi);
        unpk(A8, lo, hi);
        e4 = lsgn(lane, 0x14, lo + hi);
        e8 = lsgn(lane, 0x04, lo + hi);
        E[0] = pk(e0, e1); E[1] = pk(e2, e3); E[2] = pk(e4, e5);
        E[3] = pk(e6, e7); E[4] = pk(e8, e9);
    }
#pragma unroll
    for (int off = 16; off > 0; off >>= 1)
#pragma unroll
        for (int k = 0; k < 5; k++)
            E[k] = add2(E[k], __shfl_xor_sync(FULLM, E[k], off));

    // ---- linear head ----
    if (lane < NC) {
        float e[NQ];
#pragma unroll
        for (int k = 0; k < 5; k++) unpk(E[k], e[2 * k], e[2 * k + 1]);
        float o = __ldg(&bout[lane]);
#pragma unroll
        for (int q = 0; q < NQ; q++) o += e[q] * __ldg(&Wout[lane * NQ + q]);
        out[(size_t)b * NC + lane] = o;
    }
}

extern "C" void kernel_launch(void* const* d_in, const int* in_sizes, int n_in,
                              void* d_out, int out_size) {
    const float* x = (const float*)d_in[0];
    const float* W_proj = (const float*)d_in[1];
    const float* weights = (const float*)d_in[2];
    const float* W_out = (const float*)d_in[3];
    const float* b_out = (const float*)d_in[4];
    float* out = (float*)d_out;

    int B = in_sizes[0] / NF;
    int nblk = (B + 3) / 4;

    build_diag<<<5, 512>>>(weights);
    fused_kernel<<<nblk, 128>>>(x, W_proj, weights, W_out, b_out, out, B);
}